// round 1
// baseline (speedup 1.0000x reference)
#include <cuda_runtime.h>

#define B_     16
#define T_     65536
#define HN     64
#define CHUNKS 128
#define L_     (T_ / CHUNKS)   // 512
#define TT     32
#define DEPTH  4

// Scratch (allocation-free rule: __device__ globals)
__device__ float g_buf[(size_t)B_ * T_ * HN];        // 256 MB ping buffer (in-place per layer)
__device__ float g_ends[B_ * CHUNKS * HN];
__device__ float g_carr[B_ * CHUNKS * HN];

__device__ __forceinline__ float dot32(const float* __restrict__ w,
                                       const float* __restrict__ sv) {
    float a0 = 0.f, a1 = 0.f;
#pragma unroll
    for (int i = 0; i < 8; i++) {
        float4 v = ((const float4*)sv)[i];
        a0 = fmaf(w[4 * i + 0], v.x, a0);
        a1 = fmaf(w[4 * i + 1], v.y, a1);
        a0 = fmaf(w[4 * i + 2], v.z, a0);
        a1 = fmaf(w[4 * i + 3], v.w, a1);
    }
    return a0 + a1;
}

// ---------------------------------------------------------------------------
// Kernel 1: per-chunk zero-init end state of the diagonal scan.
// MODE 0: layer 0, input is x [B*T]; Bu = gamma*(Bm@Win)[n] * x_t
// MODE 1: input is u [B*T*64]; Bu = gamma * Bm @ u_t
// ---------------------------------------------------------------------------
template <int MODE>
__global__ void __launch_bounds__(128, 4)
k_ends(const float* __restrict__ uin, float* __restrict__ ends,
       const float* __restrict__ Bm, const float* __restrict__ nu_log,
       const float* __restrict__ gamma_log, const float* __restrict__ Win) {
    __shared__ __align__(16) float u_tile[TT * HN];
    __shared__ float win_s[HN];

    const int tid = threadIdx.x;
    const int n = tid >> 1, p = tid & 1;
    const int bc = blockIdx.x;
    const int b = bc / CHUNKS, c = bc % CHUNKS;
    const long base = (long)b * T_ + (long)c * L_;

    const float gam = expf(gamma_log[n]);
    const float A_n = expf(-expf(nu_log[n]));

    float wB[32];
    float cX = 0.f;
    if (MODE == 1) {
#pragma unroll
        for (int i = 0; i < 32; i++) wB[i] = gam * Bm[n * HN + p * 32 + i];
    } else {
        if (tid < HN) win_s[tid] = Win[tid];
        __syncthreads();
        float acc = 0.f;
#pragma unroll
        for (int i = 0; i < 32; i++)
            acc = fmaf(Bm[n * HN + p * 32 + i], win_s[p * 32 + i], acc);
        acc += __shfl_xor_sync(0xffffffffu, acc, 1);
        cX = gam * acc;
    }

    float s = 0.f;
    for (int t0 = 0; t0 < L_; t0 += TT) {
        __syncthreads();
        if (MODE == 0) {
            if (tid < TT) u_tile[tid] = uin[base + t0 + tid];
        } else {
            const float4* g = (const float4*)(uin + (base + t0) * HN);
#pragma unroll
            for (int i = 0; i < (TT * HN / 4) / 128; i++)
                ((float4*)u_tile)[i * 128 + tid] = g[i * 128 + tid];
        }
        __syncthreads();
#pragma unroll 1
        for (int tt = 0; tt < TT; tt++) {
            float bu;
            if (MODE == 0) {
                bu = cX * u_tile[tt];
            } else {
                float acc = dot32(wB, u_tile + tt * HN + p * 32);
                bu = acc + __shfl_xor_sync(0xffffffffu, acc, 1);
            }
            s = fmaf(A_n, s, bu);
        }
    }
    if (p == 0) ends[bc * HN + n] = s;
}

// ---------------------------------------------------------------------------
// Kernel 2: prefix-combine chunk states. carry_in(c) = state after chunk c-1.
// A^L computed exactly as exp(-exp(nu_log)*L).
// ---------------------------------------------------------------------------
__global__ void k_combine(const float* __restrict__ ends,
                          float* __restrict__ carries,
                          const float* __restrict__ nu_log) {
    const int b = blockIdx.x;
    const int n = threadIdx.x;
    const float e = expf(nu_log[n]);
    const float AL = expf(-e * (float)L_);
    float carry = 0.f;
#pragma unroll 8
    for (int c = 0; c < CHUNKS; c++) {
        carries[(b * CHUNKS + c) * HN + n] = carry;
        carry = fmaf(AL, carry, ends[(b * CHUNKS + c) * HN + n]);
    }
}

// ---------------------------------------------------------------------------
// Kernel 3: replay scan with carry + full per-token block math.
// MODE 0: layer 0 (reads x, writes buf)
// MODE 1: middle layer (reads buf, writes buf in-place)
// MODE 2: last layer (reads buf, writes dout = out @ Wout^T)
// Thread pair (n, p): holds Bm/Cm/Wlin half-rows in registers.
// ---------------------------------------------------------------------------
template <int MODE>
__global__ void __launch_bounds__(128, 3)
k_apply(const float* __restrict__ uin, float* __restrict__ uout,
        const float* __restrict__ carries, const float* __restrict__ Bm,
        const float* __restrict__ Cm, const float* __restrict__ Wlin,
        const float* __restrict__ nu_log, const float* __restrict__ gamma_log,
        const float* __restrict__ Dv, const float* __restrict__ blin,
        const float* __restrict__ Win, const float* __restrict__ Wout) {
    __shared__ __align__(16) float u_tile[TT * HN];
    __shared__ float o_tile[TT * 65];
    __shared__ __align__(16) float hs[HN];
    __shared__ __align__(16) float zs[HN];
    __shared__ float win_s[HN], wout_s[HN];
    __shared__ float red[4][33];

    const int tid = threadIdx.x;
    const int n = tid >> 1, p = tid & 1;
    const int bc = blockIdx.x;
    const int b = bc / CHUNKS, c = bc % CHUNKS;
    const long base = (long)b * T_ + (long)c * L_;

    const float gam = expf(gamma_log[n]);
    const float A_n = expf(-expf(nu_log[n]));
    const float Dv_n = Dv[n];
    const float blin_n = blin[n];

    float wB[32], wC[32], wW[32];
#pragma unroll
    for (int i = 0; i < 32; i++) {
        wC[i] = Cm[n * HN + p * 32 + i];
        wW[i] = Wlin[n * HN + p * 32 + i];
        if (MODE != 0) wB[i] = gam * Bm[n * HN + p * 32 + i];
    }
    if (tid < HN) {
        win_s[tid] = Win[tid];
        if (MODE == 2) wout_s[tid] = Wout[tid];
    }
    __syncthreads();

    float cX = 0.f, winn = 0.f;
    if (MODE == 0) {
        float acc = 0.f;
#pragma unroll
        for (int i = 0; i < 32; i++)
            acc = fmaf(Bm[n * HN + p * 32 + i], win_s[p * 32 + i], acc);
        acc += __shfl_xor_sync(0xffffffffu, acc, 1);
        cX = gam * acc;
        winn = win_s[n];
    }

    float h = carries[bc * HN + n];

    for (int t0 = 0; t0 < L_; t0 += TT) {
        __syncthreads();
        if (MODE == 0) {
            if (tid < TT) u_tile[tid] = uin[base + t0 + tid];
        } else {
            const float4* g = (const float4*)(uin + (base + t0) * HN);
#pragma unroll
            for (int i = 0; i < (TT * HN / 4) / 128; i++)
                ((float4*)u_tile)[i * 128 + tid] = g[i * 128 + tid];
        }
        __syncthreads();

#pragma unroll 1
        for (int tt = 0; tt < TT; tt++) {
            const float hprev = h;
            if (p == 0) hs[n] = hprev;

            float bu, u_n;
            if (MODE == 0) {
                const float xt = u_tile[tt];
                bu = cX * xt;
                u_n = winn * xt;
            } else {
                float acc = dot32(wB, u_tile + tt * HN + p * 32);
                bu = acc + __shfl_xor_sync(0xffffffffu, acc, 1);
                u_n = u_tile[tt * HN + n];
            }
            __syncthreads();  // hs visible

            float accy = dot32(wC, hs + p * 32);
            float y = accy + __shfl_xor_sync(0xffffffffu, accy, 1);
            y = fmaf(Dv_n, u_n, y);
            const float z = y * rsqrtf(fmaf(y, y, 1.0f));
            if (p == 0) zs[n] = z;
            h = fmaf(A_n, hprev, bu);
            __syncthreads();  // zs visible

            float acco = dot32(wW, zs + p * 32);
            const float outv =
                acco + __shfl_xor_sync(0xffffffffu, acco, 1) + blin_n + u_n;
            if (p == 0) o_tile[tt * 65 + n] = outv;
        }
        __syncthreads();

        if (MODE == 2) {
            // out_scalar[t] = sum_j o_tile[t][j] * Wout[j]
            const int q = tid >> 5, t = tid & 31;
            float part = 0.f;
#pragma unroll
            for (int jj = 0; jj < 16; jj++)
                part = fmaf(o_tile[t * 65 + q * 16 + jj], wout_s[q * 16 + jj], part);
            red[q][t] = part;
            __syncthreads();
            if (tid < TT)
                uout[base + t0 + tid] =
                    red[0][tid] + red[1][tid] + red[2][tid] + red[3][tid];
        } else {
#pragma unroll
            for (int i = 0; i < (TT * HN) / 128; i++) {
                const int idx = i * 128 + tid;
                uout[(base + t0) * HN + idx] = o_tile[(idx >> 6) * 65 + (idx & 63)];
            }
        }
    }
}

// ---------------------------------------------------------------------------
extern "C" void kernel_launch(void* const* d_in, const int* in_sizes, int n_in,
                              void* d_out, int out_size) {
    (void)in_sizes; (void)n_in; (void)out_size;
    const float* x     = (const float*)d_in[0];  // [16,65536,1]
    const float* Win   = (const float*)d_in[1];  // [64,1]
    const float* nu    = (const float*)d_in[2];  // [4,64]
    const float* ga    = (const float*)d_in[3];  // [4,64]
    const float* Bm    = (const float*)d_in[4];  // [4,64,64]
    const float* Cm    = (const float*)d_in[5];  // [4,64,64]
    const float* Dv    = (const float*)d_in[6];  // [4,64]
    const float* Wl    = (const float*)d_in[7];  // [4,64,64]
    const float* bl    = (const float*)d_in[8];  // [4,64]
    const float* Wo    = (const float*)d_in[9];  // [1,64]
    float* out = (float*)d_out;

    float *buf, *ends, *carr;
    cudaGetSymbolAddress((void**)&buf, g_buf);
    cudaGetSymbolAddress((void**)&ends, g_ends);
    cudaGetSymbolAddress((void**)&carr, g_carr);

    const dim3 grid(B_ * CHUNKS), blk(128);

    for (int l = 0; l < DEPTH; l++) {
        const float* Bm_l = Bm + l * HN * HN;
        const float* Cm_l = Cm + l * HN * HN;
        const float* Wl_l = Wl + l * HN * HN;
        const float* nu_l = nu + l * HN;
        const float* ga_l = ga + l * HN;
        const float* Dv_l = Dv + l * HN;
        const float* bl_l = bl + l * HN;

        if (l == 0)
            k_ends<0><<<grid, blk>>>(x, ends, Bm_l, nu_l, ga_l, Win);
        else
            k_ends<1><<<grid, blk>>>(buf, ends, Bm_l, nu_l, ga_l, Win);

        k_combine<<<B_, HN>>>(ends, carr, nu_l);

        if (l == 0)
            k_apply<0><<<grid, blk>>>(x, buf, carr, Bm_l, Cm_l, Wl_l, nu_l,
                                      ga_l, Dv_l, bl_l, Win, Wo);
        else if (l < DEPTH - 1)
            k_apply<1><<<grid, blk>>>(buf, buf, carr, Bm_l, Cm_l, Wl_l, nu_l,
                                      ga_l, Dv_l, bl_l, Win, Wo);
        else
            k_apply<2><<<grid, blk>>>(buf, out, carr, Bm_l, Cm_l, Wl_l, nu_l,
                                      ga_l, Dv_l, bl_l, Win, Wo);
    }
}

// round 2
// speedup vs baseline: 2.3427x; 2.3427x over previous
#include <cuda_runtime.h>

#define B_     16
#define T_     65536
#define HN     64
#define CHUNKS 128
#define L_     512
#define TT     32
#define NT     (L_ / TT)   // 16 tiles per chunk
#define DEPTH  4
#define BP     36          // smem tile pitch (floats), 16B-aligned rows, conflict-light

// Scratch (__device__ globals: allocation-free rule)
__device__ float g_u [(size_t)B_ * T_ * HN];   // layer activation ping buffer
__device__ float g_bu[(size_t)B_ * T_ * HN];   // precomputed Bu per layer
__device__ float g_ends[B_ * CHUNKS * HN];
__device__ float g_carr[B_ * CHUNKS * HN];

#define FMA16(c, a, b)                         \
    c[0][0] = fmaf(a.x, b.x, c[0][0]);         \
    c[0][1] = fmaf(a.x, b.y, c[0][1]);         \
    c[0][2] = fmaf(a.x, b.z, c[0][2]);         \
    c[0][3] = fmaf(a.x, b.w, c[0][3]);         \
    c[1][0] = fmaf(a.y, b.x, c[1][0]);         \
    c[1][1] = fmaf(a.y, b.y, c[1][1]);         \
    c[1][2] = fmaf(a.y, b.z, c[1][2]);         \
    c[1][3] = fmaf(a.y, b.w, c[1][3]);         \
    c[2][0] = fmaf(a.z, b.x, c[2][0]);         \
    c[2][1] = fmaf(a.z, b.y, c[2][1]);         \
    c[2][2] = fmaf(a.z, b.z, c[2][2]);         \
    c[2][3] = fmaf(a.z, b.w, c[2][3]);         \
    c[3][0] = fmaf(a.w, b.x, c[3][0]);         \
    c[3][1] = fmaf(a.w, b.y, c[3][1]);         \
    c[3][2] = fmaf(a.w, b.z, c[3][2]);         \
    c[3][3] = fmaf(a.w, b.w, c[3][3]);

// ---------------------------------------------------------------------------
// k_bu: compute Bu = gamma * (u @ Bm^T) for the whole sequence (GEMM-tiled),
// store it to g_bu in [chunk][tile][n][tok32] layout, and produce the
// per-chunk zero-init end state of the diagonal scan.
// MODE 0: layer 0, input is x [B*T]; Bu[n][t] = cX[n]*x_t with cX = gam*(Bm@Win)
// MODE 1: input is u [B*T*64]
// ---------------------------------------------------------------------------
template <int MODE>
__global__ void __launch_bounds__(128, 4)
k_bu(const float* __restrict__ uin, float* __restrict__ bu_g,
     float* __restrict__ ends, const float* __restrict__ Bm,
     const float* __restrict__ nu_log, const float* __restrict__ gamma_log,
     const float* __restrict__ Win) {
    __shared__ float wtB[64 * 64];     // [k][n] = gam[n]*Bm[n][k]; MODE0: cX in [0..63]
    __shared__ float buf[64 * BP];     // Bu tile [n][tok]
    __shared__ float us[64 * BP];      // u tile transposed [k][tok]; MODE0: x tile
    __shared__ float gam_s[64], aux[64];

    const int tid = threadIdx.x;
    const int bc  = blockIdx.x;
    const long base = (long)(bc / CHUNKS) * T_ + (long)(bc % CHUNKS) * L_;

    if (tid < 64) gam_s[tid] = expf(gamma_log[tid]);
    if (MODE == 0 && tid < 64) aux[tid] = Win[tid];
    __syncthreads();

    float A_n = 0.f, s = 0.f;
    if (tid < 64) A_n = expf(-expf(nu_log[tid]));

    if (MODE == 1) {
        for (int idx = tid; idx < 4096; idx += 128) {
            int n = idx >> 6, k = idx & 63;
            wtB[k * 64 + n] = gam_s[n] * Bm[idx];
        }
    } else {
        if (tid < 64) {
            float acc = 0.f;
#pragma unroll
            for (int k = 0; k < 64; k++) acc = fmaf(Bm[tid * 64 + k], aux[k], acc);
            wtB[tid] = gam_s[tid] * acc;   // cX[n]
        }
    }
    __syncthreads();

    const int ngrp = tid & 15, tokg = tid >> 4;

    for (int tile = 0; tile < NT; tile++) {
        const long t0 = base + (long)tile * TT;
        if (MODE == 1) {
#pragma unroll
            for (int it = 0; it < 4; it++) {
                int idx = it * 128 + tid;             // 0..511
                int t = idx >> 4, nq = idx & 15;
                float4 v = *(const float4*)(uin + (t0 + t) * HN + nq * 4);
                us[(nq * 4 + 0) * BP + t] = v.x;
                us[(nq * 4 + 1) * BP + t] = v.y;
                us[(nq * 4 + 2) * BP + t] = v.z;
                us[(nq * 4 + 3) * BP + t] = v.w;
            }
            __syncthreads();
            float c[4][4] = {};
#pragma unroll 4
            for (int k = 0; k < 64; k++) {
                float4 a = *(const float4*)(us + k * BP + tokg * 4);
                float4 b = *(const float4*)(wtB + k * 64 + ngrp * 4);
                FMA16(c, a, b)
            }
#pragma unroll
            for (int j = 0; j < 4; j++) {
#pragma unroll
                for (int i = 0; i < 4; i++)
                    buf[(ngrp * 4 + j) * BP + tokg * 4 + i] = c[i][j];
            }
        } else {
            if (tid < 32) us[tid] = uin[t0 + tid];
            __syncthreads();
            for (int idx = tid; idx < 2048; idx += 128) {
                int n = idx >> 5, t = idx & 31;
                buf[n * BP + t] = wtB[n] * us[t];
            }
        }
        __syncthreads();

        // store Bu tile [n][tok] coalesced
        const size_t bbase = ((size_t)bc * NT + tile) * 2048;
#pragma unroll
        for (int it = 0; it < 4; it++) {
            int off = it * 512 + tid * 4;
            int n = off >> 5, t = off & 31;
            float4 v = *(const float4*)(buf + n * BP + t);
            *(float4*)(bu_g + bbase + off) = v;
        }
        // running end-state scan (Horner)
        if (tid < 64) {
#pragma unroll
            for (int t = 0; t < TT; t++) s = fmaf(A_n, s, buf[tid * BP + t]);
        }
        __syncthreads();
    }
    if (tid < 64) ends[bc * 64 + tid] = s;
}

// ---------------------------------------------------------------------------
// k_combine: prefix-combine chunk states (A constant -> A^L closed form)
// ---------------------------------------------------------------------------
__global__ void k_combine(const float* __restrict__ ends,
                          float* __restrict__ carries,
                          const float* __restrict__ nu_log) {
    const int b = blockIdx.x, n = threadIdx.x;
    const float AL = expf(-expf(nu_log[n]) * (float)L_);
    float carry = 0.f;
#pragma unroll 8
    for (int c = 0; c < CHUNKS; c++) {
        carries[(b * CHUNKS + c) * HN + n] = carry;
        carry = fmaf(AL, carry, ends[(b * CHUNKS + c) * HN + n]);
    }
}

// ---------------------------------------------------------------------------
// k_apply: load Bu, scan h with carry, y = hprev@Cm^T + Dv*u, z = tanh~(y),
// out = z@Wlin^T + blin + u.  MODE 0: first layer (u from x*Win^T).
// MODE 1: middle (in-place on g_u). MODE 2: last (project with Wout).
// ---------------------------------------------------------------------------
template <int MODE>
__global__ void __launch_bounds__(128, 4)
k_apply(const float* __restrict__ uin, const float* __restrict__ bu_g,
        float* __restrict__ uout, const float* __restrict__ carr,
        const float* __restrict__ Cm, const float* __restrict__ Wl,
        const float* __restrict__ nu_log, const float* __restrict__ Dv,
        const float* __restrict__ blin, const float* __restrict__ Win,
        const float* __restrict__ Wout) {
    __shared__ float wtC[4096], wtW[4096];   // [k][n]
    __shared__ float buf[64 * BP];           // Bu -> hprev -> z, all [n/k][tok]
    __shared__ float dv_s[64], bl_s[64], w2_s[64];
    __shared__ float x_s[32];

    const int tid = threadIdx.x;
    const int bc  = blockIdx.x;
    const long base = (long)(bc / CHUNKS) * T_ + (long)(bc % CHUNKS) * L_;

    if (tid < 64) {
        dv_s[tid] = Dv[tid];
        bl_s[tid] = blin[tid];
        w2_s[tid] = (MODE == 0) ? Win[tid] : ((MODE == 2) ? Wout[tid] : 0.f);
    }
    for (int idx = tid; idx < 4096; idx += 128) {
        int n = idx >> 6, k = idx & 63;
        wtC[k * 64 + n] = Cm[idx];
        wtW[k * 64 + n] = Wl[idx];
    }
    float A_n = 0.f, h = 0.f;
    if (tid < 64) {
        A_n = expf(-expf(nu_log[tid]));
        h = carr[bc * 64 + tid];
    }
    __syncthreads();

    const int ngrp = tid & 15, tokg = tid >> 4;
    float dvr[4], blr[4], w2r[4];
#pragma unroll
    for (int j = 0; j < 4; j++) {
        dvr[j] = dv_s[ngrp * 4 + j];
        blr[j] = bl_s[ngrp * 4 + j];
        w2r[j] = w2_s[ngrp * 4 + j];
    }

    for (int tile = 0; tile < NT; tile++) {
        const long t0 = base + (long)tile * TT;
        const size_t bbase = ((size_t)bc * NT + tile) * 2048;

        // load Bu tile -> buf [n][tok]
#pragma unroll
        for (int it = 0; it < 4; it++) {
            int off = it * 512 + tid * 4;
            float4 v = *(const float4*)(bu_g + bbase + off);
            *(float4*)(buf + (off >> 5) * BP + (off & 31)) = v;
        }
        // u tile in registers (4 toks x 4 ns per thread)
        float ur[4][4];
        if (MODE == 0) {
            if (tid < 32) x_s[tid] = uin[t0 + tid];
        } else {
#pragma unroll
            for (int i = 0; i < 4; i++) {
                float4 v = *(const float4*)(uin + (t0 + tokg * 4 + i) * HN + ngrp * 4);
                ur[i][0] = v.x; ur[i][1] = v.y; ur[i][2] = v.z; ur[i][3] = v.w;
            }
        }
        __syncthreads();
        if (MODE == 0) {
#pragma unroll
            for (int i = 0; i < 4; i++) {
                float xv = x_s[tokg * 4 + i];
#pragma unroll
                for (int j = 0; j < 4; j++) ur[i][j] = xv * w2r[j];
            }
        }
        // sequential scan over the tile: buf <- hprev
        if (tid < 64) {
#pragma unroll
            for (int t = 0; t < TT; t++) {
                float b = buf[tid * BP + t];
                buf[tid * BP + t] = h;
                h = fmaf(A_n, h, b);
            }
        }
        __syncthreads();

        // y = hprev @ Cm^T
        float c[4][4] = {};
#pragma unroll 4
        for (int k = 0; k < 64; k++) {
            float4 a = *(const float4*)(buf + k * BP + tokg * 4);
            float4 b = *(const float4*)(wtC + k * 64 + ngrp * 4);
            FMA16(c, a, b)
        }
        // z = tanh~(y + Dv*u)
#pragma unroll
        for (int i = 0; i < 4; i++)
#pragma unroll
            for (int j = 0; j < 4; j++) {
                float y = fmaf(dvr[j], ur[i][j], c[i][j]);
                c[i][j] = y * rsqrtf(fmaf(y, y, 1.0f));
            }
        __syncthreads();  // all y-GEMM reads of buf done
#pragma unroll
        for (int j = 0; j < 4; j++)
#pragma unroll
            for (int i = 0; i < 4; i++)
                buf[(ngrp * 4 + j) * BP + tokg * 4 + i] = c[i][j];
        __syncthreads();

        // out = z @ Wlin^T + blin + u
        float o[4][4] = {};
#pragma unroll 4
        for (int k = 0; k < 64; k++) {
            float4 a = *(const float4*)(buf + k * BP + tokg * 4);
            float4 b = *(const float4*)(wtW + k * 64 + ngrp * 4);
            FMA16(o, a, b)
        }
#pragma unroll
        for (int i = 0; i < 4; i++)
#pragma unroll
            for (int j = 0; j < 4; j++) o[i][j] += blr[j] + ur[i][j];

        if (MODE == 2) {
#pragma unroll
            for (int i = 0; i < 4; i++) {
                float p = o[i][0] * w2r[0] + o[i][1] * w2r[1] +
                          o[i][2] * w2r[2] + o[i][3] * w2r[3];
                p += __shfl_xor_sync(0xffffffffu, p, 1);
                p += __shfl_xor_sync(0xffffffffu, p, 2);
                p += __shfl_xor_sync(0xffffffffu, p, 4);
                p += __shfl_xor_sync(0xffffffffu, p, 8);
                if (ngrp == 0) uout[t0 + tokg * 4 + i] = p;
            }
        } else {
#pragma unroll
            for (int i = 0; i < 4; i++) {
                float4 v = make_float4(o[i][0], o[i][1], o[i][2], o[i][3]);
                *(float4*)(uout + (t0 + tokg * 4 + i) * HN + ngrp * 4) = v;
            }
        }
        __syncthreads();
    }
}

// ---------------------------------------------------------------------------
extern "C" void kernel_launch(void* const* d_in, const int* in_sizes, int n_in,
                              void* d_out, int out_size) {
    (void)in_sizes; (void)n_in; (void)out_size;
    const float* x   = (const float*)d_in[0];
    const float* Win = (const float*)d_in[1];
    const float* nu  = (const float*)d_in[2];
    const float* ga  = (const float*)d_in[3];
    const float* Bm  = (const float*)d_in[4];
    const float* Cm  = (const float*)d_in[5];
    const float* Dv  = (const float*)d_in[6];
    const float* Wl  = (const float*)d_in[7];
    const float* bl  = (const float*)d_in[8];
    const float* Wo  = (const float*)d_in[9];
    float* out = (float*)d_out;

    float *u, *bu, *ends, *carr;
    cudaGetSymbolAddress((void**)&u, g_u);
    cudaGetSymbolAddress((void**)&bu, g_bu);
    cudaGetSymbolAddress((void**)&ends, g_ends);
    cudaGetSymbolAddress((void**)&carr, g_carr);

    const dim3 grid(B_ * CHUNKS), blk(128);

    for (int l = 0; l < DEPTH; l++) {
        const float* Bm_l = Bm + l * HN * HN;
        const float* Cm_l = Cm + l * HN * HN;
        const float* Wl_l = Wl + l * HN * HN;
        const float* nu_l = nu + l * HN;
        const float* ga_l = ga + l * HN;
        const float* Dv_l = Dv + l * HN;
        const float* bl_l = bl + l * HN;

        if (l == 0)
            k_bu<0><<<grid, blk>>>(x, bu, ends, Bm_l, nu_l, ga_l, Win);
        else
            k_bu<1><<<grid, blk>>>(u, bu, ends, Bm_l, nu_l, ga_l, Win);

        k_combine<<<B_, HN>>>(ends, carr, nu_l);

        if (l == 0)
            k_apply<0><<<grid, blk>>>(x, bu, u, carr, Cm_l, Wl_l, nu_l, Dv_l,
                                      bl_l, Win, Wo);
        else if (l < DEPTH - 1)
            k_apply<1><<<grid, blk>>>(u, bu, u, carr, Cm_l, Wl_l, nu_l, Dv_l,
                                      bl_l, Win, Wo);
        else
            k_apply<2><<<grid, blk>>>(u, bu, out, carr, Cm_l, Wl_l, nu_l, Dv_l,
                                      bl_l, Win, Wo);
    }
}

// round 3
// speedup vs baseline: 2.3430x; 1.0001x over previous
#include <cuda_runtime.h>

#define B_     16
#define T_     65536
#define HN     64
#define CHUNKS 128
#define L_     512
#define TT     32
#define NT     (L_ / TT)   // 16 tiles per chunk
#define DEPTH  4
#define BP     36          // smem tile pitch (floats), 16B-aligned rows, conflict-light

// Scratch (__device__ globals: allocation-free rule)
__device__ float g_u [(size_t)B_ * T_ * HN];   // layer activation ping buffer
__device__ float g_bu[(size_t)B_ * T_ * HN];   // precomputed Bu per layer
__device__ float g_ends[B_ * CHUNKS * HN];
__device__ float g_carr[B_ * CHUNKS * HN];

#define FMA16(c, a, b)                         \
    c[0][0] = fmaf(a.x, b.x, c[0][0]);         \
    c[0][1] = fmaf(a.x, b.y, c[0][1]);         \
    c[0][2] = fmaf(a.x, b.z, c[0][2]);         \
    c[0][3] = fmaf(a.x, b.w, c[0][3]);         \
    c[1][0] = fmaf(a.y, b.x, c[1][0]);         \
    c[1][1] = fmaf(a.y, b.y, c[1][1]);         \
    c[1][2] = fmaf(a.y, b.z, c[1][2]);         \
    c[1][3] = fmaf(a.y, b.w, c[1][3]);         \
    c[2][0] = fmaf(a.z, b.x, c[2][0]);         \
    c[2][1] = fmaf(a.z, b.y, c[2][1]);         \
    c[2][2] = fmaf(a.z, b.z, c[2][2]);         \
    c[2][3] = fmaf(a.z, b.w, c[2][3]);         \
    c[3][0] = fmaf(a.w, b.x, c[3][0]);         \
    c[3][1] = fmaf(a.w, b.y, c[3][1]);         \
    c[3][2] = fmaf(a.w, b.z, c[3][2]);         \
    c[3][3] = fmaf(a.w, b.w, c[3][3]);

// ---------------------------------------------------------------------------
// k_bu: compute Bu = gamma * (u @ Bm^T) for the whole sequence (GEMM-tiled),
// store it to g_bu in [chunk][tile][n][tok32] layout, and produce the
// per-chunk zero-init end state of the diagonal scan.
// MODE 0: layer 0, input is x [B*T]; Bu[n][t] = cX[n]*x_t with cX = gam*(Bm@Win)
// MODE 1: input is u [B*T*64]
// ---------------------------------------------------------------------------
template <int MODE>
__global__ void __launch_bounds__(128, 4)
k_bu(const float* __restrict__ uin, float* __restrict__ bu_g,
     float* __restrict__ ends, const float* __restrict__ Bm,
     const float* __restrict__ nu_log, const float* __restrict__ gamma_log,
     const float* __restrict__ Win) {
    __shared__ float wtB[64 * 64];     // [k][n] = gam[n]*Bm[n][k]; MODE0: cX in [0..63]
    __shared__ float buf[64 * BP];     // Bu tile [n][tok]
    __shared__ float us[64 * BP];      // u tile transposed [k][tok]; MODE0: x tile
    __shared__ float gam_s[64], aux[64];

    const int tid = threadIdx.x;
    const int bc  = blockIdx.x;
    const long base = (long)(bc / CHUNKS) * T_ + (long)(bc % CHUNKS) * L_;

    if (tid < 64) gam_s[tid] = expf(gamma_log[tid]);
    if (MODE == 0 && tid < 64) aux[tid] = Win[tid];
    __syncthreads();

    float A_n = 0.f, s = 0.f;
    if (tid < 64) A_n = expf(-expf(nu_log[tid]));

    if (MODE == 1) {
        for (int idx = tid; idx < 4096; idx += 128) {
            int n = idx >> 6, k = idx & 63;
            wtB[k * 64 + n] = gam_s[n] * Bm[idx];
        }
    } else {
        if (tid < 64) {
            float acc = 0.f;
#pragma unroll
            for (int k = 0; k < 64; k++) acc = fmaf(Bm[tid * 64 + k], aux[k], acc);
            wtB[tid] = gam_s[tid] * acc;   // cX[n]
        }
    }
    __syncthreads();

    const int ngrp = tid & 15, tokg = tid >> 4;

    for (int tile = 0; tile < NT; tile++) {
        const long t0 = base + (long)tile * TT;
        if (MODE == 1) {
#pragma unroll
            for (int it = 0; it < 4; it++) {
                int idx = it * 128 + tid;             // 0..511
                int t = idx >> 4, nq = idx & 15;
                float4 v = *(const float4*)(uin + (t0 + t) * HN + nq * 4);
                us[(nq * 4 + 0) * BP + t] = v.x;
                us[(nq * 4 + 1) * BP + t] = v.y;
                us[(nq * 4 + 2) * BP + t] = v.z;
                us[(nq * 4 + 3) * BP + t] = v.w;
            }
            __syncthreads();
            float c[4][4] = {};
#pragma unroll 4
            for (int k = 0; k < 64; k++) {
                float4 a = *(const float4*)(us + k * BP + tokg * 4);
                float4 b = *(const float4*)(wtB + k * 64 + ngrp * 4);
                FMA16(c, a, b)
            }
#pragma unroll
            for (int j = 0; j < 4; j++) {
#pragma unroll
                for (int i = 0; i < 4; i++)
                    buf[(ngrp * 4 + j) * BP + tokg * 4 + i] = c[i][j];
            }
        } else {
            if (tid < 32) us[tid] = uin[t0 + tid];
            __syncthreads();
            for (int idx = tid; idx < 2048; idx += 128) {
                int n = idx >> 5, t = idx & 31;
                buf[n * BP + t] = wtB[n] * us[t];
            }
        }
        __syncthreads();

        // store Bu tile [n][tok] coalesced
        const size_t bbase = ((size_t)bc * NT + tile) * 2048;
#pragma unroll
        for (int it = 0; it < 4; it++) {
            int off = it * 512 + tid * 4;
            int n = off >> 5, t = off & 31;
            float4 v = *(const float4*)(buf + n * BP + t);
            *(float4*)(bu_g + bbase + off) = v;
        }
        // running end-state scan (Horner)
        if (tid < 64) {
#pragma unroll
            for (int t = 0; t < TT; t++) s = fmaf(A_n, s, buf[tid * BP + t]);
        }
        __syncthreads();
    }
    if (tid < 64) ends[bc * 64 + tid] = s;
}

// ---------------------------------------------------------------------------
// k_combine: prefix-combine chunk states (A constant -> A^L closed form)
// ---------------------------------------------------------------------------
__global__ void k_combine(const float* __restrict__ ends,
                          float* __restrict__ carries,
                          const float* __restrict__ nu_log) {
    const int b = blockIdx.x, n = threadIdx.x;
    const float AL = expf(-expf(nu_log[n]) * (float)L_);
    float carry = 0.f;
#pragma unroll 8
    for (int c = 0; c < CHUNKS; c++) {
        carries[(b * CHUNKS + c) * HN + n] = carry;
        carry = fmaf(AL, carry, ends[(b * CHUNKS + c) * HN + n]);
    }
}

// ---------------------------------------------------------------------------
// k_apply: load Bu, scan h with carry, y = hprev@Cm^T + Dv*u, z = tanh~(y),
// out = z@Wlin^T + blin + u.  MODE 0: first layer (u from x*Win^T).
// MODE 1: middle (in-place on g_u). MODE 2: last (project with Wout).
// ---------------------------------------------------------------------------
template <int MODE>
__global__ void __launch_bounds__(128, 4)
k_apply(const float* __restrict__ uin, const float* __restrict__ bu_g,
        float* __restrict__ uout, const float* __restrict__ carr,
        const float* __restrict__ Cm, const float* __restrict__ Wl,
        const float* __restrict__ nu_log, const float* __restrict__ Dv,
        const float* __restrict__ blin, const float* __restrict__ Win,
        const float* __restrict__ Wout) {
    __shared__ float wtC[4096], wtW[4096];   // [k][n]
    __shared__ float buf[64 * BP];           // Bu -> hprev -> z, all [n/k][tok]
    __shared__ float dv_s[64], bl_s[64], w2_s[64];
    __shared__ float x_s[32];

    const int tid = threadIdx.x;
    const int bc  = blockIdx.x;
    const long base = (long)(bc / CHUNKS) * T_ + (long)(bc % CHUNKS) * L_;

    if (tid < 64) {
        dv_s[tid] = Dv[tid];
        bl_s[tid] = blin[tid];
        w2_s[tid] = (MODE == 0) ? Win[tid] : ((MODE == 2) ? Wout[tid] : 0.f);
    }
    for (int idx = tid; idx < 4096; idx += 128) {
        int n = idx >> 6, k = idx & 63;
        wtC[k * 64 + n] = Cm[idx];
        wtW[k * 64 + n] = Wl[idx];
    }
    float A_n = 0.f, h = 0.f;
    if (tid < 64) {
        A_n = expf(-expf(nu_log[tid]));
        h = carr[bc * 64 + tid];
    }
    __syncthreads();

    const int ngrp = tid & 15, tokg = tid >> 4;
    float dvr[4], blr[4], w2r[4];
#pragma unroll
    for (int j = 0; j < 4; j++) {
        dvr[j] = dv_s[ngrp * 4 + j];
        blr[j] = bl_s[ngrp * 4 + j];
        w2r[j] = w2_s[ngrp * 4 + j];
    }

    for (int tile = 0; tile < NT; tile++) {
        const long t0 = base + (long)tile * TT;
        const size_t bbase = ((size_t)bc * NT + tile) * 2048;

        // load Bu tile -> buf [n][tok]
#pragma unroll
        for (int it = 0; it < 4; it++) {
            int off = it * 512 + tid * 4;
            float4 v = *(const float4*)(bu_g + bbase + off);
            *(float4*)(buf + (off >> 5) * BP + (off & 31)) = v;
        }
        // u tile in registers (4 toks x 4 ns per thread)
        float ur[4][4];
        if (MODE == 0) {
            if (tid < 32) x_s[tid] = uin[t0 + tid];
        } else {
#pragma unroll
            for (int i = 0; i < 4; i++) {
                float4 v = *(const float4*)(uin + (t0 + tokg * 4 + i) * HN + ngrp * 4);
                ur[i][0] = v.x; ur[i][1] = v.y; ur[i][2] = v.z; ur[i][3] = v.w;
            }
        }
        __syncthreads();
        if (MODE == 0) {
#pragma unroll
            for (int i = 0; i < 4; i++) {
                float xv = x_s[tokg * 4 + i];
#pragma unroll
                for (int j = 0; j < 4; j++) ur[i][j] = xv * w2r[j];
            }
        }
        // sequential scan over the tile: buf <- hprev
        if (tid < 64) {
#pragma unroll
            for (int t = 0; t < TT; t++) {
                float b = buf[tid * BP + t];
                buf[tid * BP + t] = h;
                h = fmaf(A_n, h, b);
            }
        }
        __syncthreads();

        // y = hprev @ Cm^T
        float c[4][4] = {};
#pragma unroll 4
        for (int k = 0; k < 64; k++) {
            float4 a = *(const float4*)(buf + k * BP + tokg * 4);
            float4 b = *(const float4*)(wtC + k * 64 + ngrp * 4);
            FMA16(c, a, b)
        }
        // z = tanh~(y + Dv*u)
#pragma unroll
        for (int i = 0; i < 4; i++)
#pragma unroll
            for (int j = 0; j < 4; j++) {
                float y = fmaf(dvr[j], ur[i][j], c[i][j]);
                c[i][j] = y * rsqrtf(fmaf(y, y, 1.0f));
            }
        __syncthreads();  // all y-GEMM reads of buf done
#pragma unroll
        for (int j = 0; j < 4; j++)
#pragma unroll
            for (int i = 0; i < 4; i++)
                buf[(ngrp * 4 + j) * BP + tokg * 4 + i] = c[i][j];
        __syncthreads();

        // out = z @ Wlin^T + blin + u
        float o[4][4] = {};
#pragma unroll 4
        for (int k = 0; k < 64; k++) {
            float4 a = *(const float4*)(buf + k * BP + tokg * 4);
            float4 b = *(const float4*)(wtW + k * 64 + ngrp * 4);
            FMA16(o, a, b)
        }
#pragma unroll
        for (int i = 0; i < 4; i++)
#pragma unroll
            for (int j = 0; j < 4; j++) o[i][j] += blr[j] + ur[i][j];

        if (MODE == 2) {
#pragma unroll
            for (int i = 0; i < 4; i++) {
                float p = o[i][0] * w2r[0] + o[i][1] * w2r[1] +
                          o[i][2] * w2r[2] + o[i][3] * w2r[3];
                p += __shfl_xor_sync(0xffffffffu, p, 1);
                p += __shfl_xor_sync(0xffffffffu, p, 2);
                p += __shfl_xor_sync(0xffffffffu, p, 4);
                p += __shfl_xor_sync(0xffffffffu, p, 8);
                if (ngrp == 0) uout[t0 + tokg * 4 + i] = p;
            }
        } else {
#pragma unroll
            for (int i = 0; i < 4; i++) {
                float4 v = make_float4(o[i][0], o[i][1], o[i][2], o[i][3]);
                *(float4*)(uout + (t0 + tokg * 4 + i) * HN + ngrp * 4) = v;
            }
        }
        __syncthreads();
    }
}

// ---------------------------------------------------------------------------
extern "C" void kernel_launch(void* const* d_in, const int* in_sizes, int n_in,
                              void* d_out, int out_size) {
    (void)in_sizes; (void)n_in; (void)out_size;
    const float* x   = (const float*)d_in[0];
    const float* Win = (const float*)d_in[1];
    const float* nu  = (const float*)d_in[2];
    const float* ga  = (const float*)d_in[3];
    const float* Bm  = (const float*)d_in[4];
    const float* Cm  = (const float*)d_in[5];
    const float* Dv  = (const float*)d_in[6];
    const float* Wl  = (const float*)d_in[7];
    const float* bl  = (const float*)d_in[8];
    const float* Wo  = (const float*)d_in[9];
    float* out = (float*)d_out;

    float *u, *bu, *ends, *carr;
    cudaGetSymbolAddress((void**)&u, g_u);
    cudaGetSymbolAddress((void**)&bu, g_bu);
    cudaGetSymbolAddress((void**)&ends, g_ends);
    cudaGetSymbolAddress((void**)&carr, g_carr);

    const dim3 grid(B_ * CHUNKS), blk(128);

    for (int l = 0; l < DEPTH; l++) {
        const float* Bm_l = Bm + l * HN * HN;
        const float* Cm_l = Cm + l * HN * HN;
        const float* Wl_l = Wl + l * HN * HN;
        const float* nu_l = nu + l * HN;
        const float* ga_l = ga + l * HN;
        const float* Dv_l = Dv + l * HN;
        const float* bl_l = bl + l * HN;

        if (l == 0)
            k_bu<0><<<grid, blk>>>(x, bu, ends, Bm_l, nu_l, ga_l, Win);
        else
            k_bu<1><<<grid, blk>>>(u, bu, ends, Bm_l, nu_l, ga_l, Win);

        k_combine<<<B_, HN>>>(ends, carr, nu_l);

        if (l == 0)
            k_apply<0><<<grid, blk>>>(x, bu, u, carr, Cm_l, Wl_l, nu_l, Dv_l,
                                      bl_l, Win, Wo);
        else if (l < DEPTH - 1)
            k_apply<1><<<grid, blk>>>(u, bu, u, carr, Cm_l, Wl_l, nu_l, Dv_l,
                                      bl_l, Win, Wo);
        else
            k_apply<2><<<grid, blk>>>(u, bu, out, carr, Cm_l, Wl_l, nu_l, Dv_l,
                                      bl_l, Win, Wo);
    }
}

// round 4
// speedup vs baseline: 3.4925x; 1.4906x over previous
#include <cuda_runtime.h>

#define B_     16
#define T_     65536
#define CHUNKS 128
#define L_     512
#define TILE   128
#define NTIL   4
#define PB     132
typedef unsigned long long ull;

__device__ float g_u [(size_t)B_ * T_ * 64];
__device__ float g_bu[(size_t)B_ * T_ * 64];
__device__ float g_ends[B_ * CHUNKS * 64];
__device__ float g_carr[B_ * CHUNKS * 64];

__device__ __forceinline__ void fma2(ull& d, ull a, ull b) {
    asm("fma.rn.f32x2 %0, %1, %2, %0;" : "+l"(d) : "l"(a), "l"(b));
}
__device__ __forceinline__ ull add2(ull a, ull b) {
    ull d; asm("add.rn.f32x2 %0, %1, %2;" : "=l"(d) : "l"(a), "l"(b)); return d;
}
__device__ __forceinline__ ull mul2(ull a, ull b) {
    ull d; asm("mul.rn.f32x2 %0, %1, %2;" : "=l"(d) : "l"(a), "l"(b)); return d;
}
__device__ __forceinline__ ull dup2(float x) {
    ull r; asm("mov.b64 %0, {%1, %1};" : "=l"(r) : "f"(x)); return r;
}
__device__ __forceinline__ float2 unp(ull p) {
    float2 r; asm("mov.b64 {%0, %1}, %2;" : "=f"(r.x), "=f"(r.y) : "l"(p)); return r;
}
__device__ __forceinline__ ull pk(float a, float b) {
    ull r; asm("mov.b64 %0, {%1, %2};" : "=l"(r) : "f"(a), "f"(b)); return r;
}

// 8tok x 8n register-tile GEMM over 64 k. BUF: [k][128 tok] rows pitch PB,
// quad q swizzled as q ^ ((k>>2)&7). wt: [k][n] pitch 64 (no swizzle).
__device__ __forceinline__ void gemm8x8(const float* __restrict__ BUF,
                                        const float* __restrict__ wt,
                                        int g_t, int g_n, ull acc[4][8]) {
#pragma unroll 4
    for (int k = 0; k < 64; k++) {
        const int m = (k >> 2) & 7;
        const float* r = BUF + k * PB;
        ulonglong2 a0 = *(const ulonglong2*)(r + 4 * ((2 * g_t) ^ m));
        ulonglong2 a1 = *(const ulonglong2*)(r + 4 * ((2 * g_t + 1) ^ m));
        float4 b0 = *(const float4*)(wt + k * 64 + 4 * g_n);
        float4 b1 = *(const float4*)(wt + k * 64 + 32 + 4 * g_n);
        ull ap[4] = {a0.x, a0.y, a1.x, a1.y};
        ull bb[8] = {dup2(b0.x), dup2(b0.y), dup2(b0.z), dup2(b0.w),
                     dup2(b1.x), dup2(b1.y), dup2(b1.z), dup2(b1.w)};
#pragma unroll
        for (int q = 0; q < 8; q++)
#pragma unroll
            for (int ii = 0; ii < 4; ii++) fma2(acc[ii][q], ap[ii], bb[q]);
    }
}

// store thread tile into BUF rows jq (n), swizzled; conflict-free per phase.
__device__ __forceinline__ void stile(float* __restrict__ BUF, int g_t, int g_n,
                                      const ull acc[4][8]) {
#pragma unroll
    for (int q = 0; q < 8; q++) {
        const int jq = (q < 4) ? 4 * g_n + q : 28 + 4 * g_n + q;
        const int mj = (jq >> 2) & 7;
        ulonglong2 v0; v0.x = acc[0][q]; v0.y = acc[1][q];
        ulonglong2 v1; v1.x = acc[2][q]; v1.y = acc[3][q];
        *(ulonglong2*)(BUF + jq * PB + 4 * ((2 * g_t) ^ mj)) = v0;
        *(ulonglong2*)(BUF + jq * PB + 4 * ((2 * g_t + 1) ^ mj)) = v1;
    }
}

// u operand loader: 4 packs (8 tokens) for output-row jq.
template <int MODE>
__device__ __forceinline__ void ldu(ull up[4], const float* __restrict__ uin,
                                    size_t toff, int jq, int i0,
                                    const float* __restrict__ XS, float w) {
    if (MODE == 0) {
        ull wp = dup2(w);
        up[0] = mul2(wp, *(const ull*)(XS + i0));
        up[1] = mul2(wp, *(const ull*)(XS + i0 + 2));
        up[2] = mul2(wp, *(const ull*)(XS + i0 + 4));
        up[3] = mul2(wp, *(const ull*)(XS + i0 + 6));
    } else {
        const float* p = uin + toff + (size_t)jq * TILE + i0;
        ulonglong2 a = *(const ulonglong2*)p;
        ulonglong2 b = *(const ulonglong2*)(p + 4);
        up[0] = a.x; up[1] = a.y; up[2] = b.x; up[3] = b.y;
    }
}

// ---------------------------------------------------------------------------
__global__ void __launch_bounds__(128)
k_init(const float* __restrict__ x, float* __restrict__ bu,
       float* __restrict__ ends, const float* __restrict__ Bm,
       const float* __restrict__ nu_log, const float* __restrict__ ga_log,
       const float* __restrict__ Win) {
    __shared__ float xs[TILE];
    __shared__ float cX[64];
    const int tid = threadIdx.x;
    const int bc = blockIdx.x;
    const long tokbase = (long)(bc / CHUNKS) * T_ + (long)(bc % CHUNKS) * L_;

    float A = 0.f, s = 0.f;
    if (tid < 64) {
        float a = 0.f;
#pragma unroll
        for (int k = 0; k < 64; k++) a = fmaf(Bm[tid * 64 + k], Win[k], a);
        cX[tid] = expf(ga_log[tid]) * a;
        A = expf(-expf(nu_log[tid]));
    }
    for (int tl = 0; tl < NTIL; tl++) {
        __syncthreads();
        xs[tid] = x[tokbase + tl * TILE + tid];
        __syncthreads();
        const size_t toff = ((size_t)bc * NTIL + tl) * (64 * TILE);
#pragma unroll
        for (int it = 0; it < 16; it++) {
            int idx = it * 512 + tid * 4;
            int row = idx >> 7, col = idx & 127;
            float c = cX[row];
            float4 v = make_float4(c * xs[col], c * xs[col + 1],
                                   c * xs[col + 2], c * xs[col + 3]);
            *(float4*)(bu + toff + idx) = v;
        }
        if (tid < 64) {
            const float c = cX[tid];
#pragma unroll 8
            for (int t = 0; t < TILE; t++) s = fmaf(A, s, c * xs[t]);
        }
    }
    if (tid < 64) ends[bc * 64 + tid] = s;
}

__global__ void k_combine(const float* __restrict__ ends,
                          float* __restrict__ carries,
                          const float* __restrict__ nu_log) {
    const int b = blockIdx.x, n = threadIdx.x;
    const float AL = expf(-expf(nu_log[n]) * (float)L_);
    float carry = 0.f;
#pragma unroll 8
    for (int c = 0; c < CHUNKS; c++) {
        carries[(b * CHUNKS + c) * 64 + n] = carry;
        carry = fmaf(AL, carry, ends[(b * CHUNKS + c) * 64 + n]);
    }
}

// ---------------------------------------------------------------------------
// Fused per-layer kernel. MODE 0: first layer (u = Win*x). MODE 1: middle.
// MODE 2: last layer (project with Wout, no next-layer Bu).
// ---------------------------------------------------------------------------
#define SMEMB 84752

template <int MODE>
__global__ void __launch_bounds__(128, 2)
k_apply(const float* __restrict__ xin, const float* __restrict__ uin,
        float* __restrict__ uout, float* __restrict__ bu,
        const float* __restrict__ carr, float* __restrict__ ends,
        const float* __restrict__ Cm, const float* __restrict__ Wl,
        const float* __restrict__ Dv, const float* __restrict__ bl,
        const float* __restrict__ nu_log, const float* __restrict__ Win,
        const float* __restrict__ Wout, const float* __restrict__ Bm_nx,
        const float* __restrict__ ga_nx, const float* __restrict__ nu_nx) {
    extern __shared__ __align__(16) float sm[];
    float* wtC = sm;            // [k][n] 4096
    float* wtW = sm + 4096;
    float* wtB = sm + 8192;
    float* BUF = sm + 12288;    // 64 * PB
    float* XS  = sm + 20736;    // 128
    float* DVs = sm + 20864;
    float* BLs = DVs + 64;
    float* W2s = BLs + 64;
    float* WLO = W2s + 64;
    float* GMs = WLO + 64;
    float* AUX = GMs + 64;

    const int tid = threadIdx.x;
    const int g_t = tid >> 3, g_n = tid & 7;
    const int i0 = g_t * 8;
    const int bc = blockIdx.x;
    const long tokbase = (long)(bc / CHUNKS) * T_ + (long)(bc % CHUNKS) * L_;

    if (tid < 64) {
        DVs[tid] = Dv[tid];
        BLs[tid] = bl[tid];
        W2s[tid] = (MODE == 0) ? Win[tid] : ((MODE == 2) ? Wout[tid] : 0.f);
        GMs[tid] = (MODE != 2) ? expf(ga_nx[tid]) : 0.f;
    }
    __syncthreads();
    // transposed weight loads: thread handles one source row -> smem column
    {
        const int r = tid & 63;
        const float* src = (tid < 64) ? Cm : Wl;
        float* dst = (tid < 64) ? wtC : wtW;
#pragma unroll 4
        for (int kq = 0; kq < 16; kq++) {
            float4 w = *(const float4*)(src + r * 64 + kq * 4);
            dst[(kq * 4 + 0) * 64 + r] = w.x;
            dst[(kq * 4 + 1) * 64 + r] = w.y;
            dst[(kq * 4 + 2) * 64 + r] = w.z;
            dst[(kq * 4 + 3) * 64 + r] = w.w;
        }
        if (MODE != 2 && tid < 64) {
            const float g = GMs[r];
#pragma unroll 4
            for (int kq = 0; kq < 16; kq++) {
                float4 w = *(const float4*)(Bm_nx + r * 64 + kq * 4);
                wtB[(kq * 4 + 0) * 64 + r] = g * w.x;
                wtB[(kq * 4 + 1) * 64 + r] = g * w.y;
                wtB[(kq * 4 + 2) * 64 + r] = g * w.z;
                wtB[(kq * 4 + 3) * 64 + r] = g * w.w;
            }
        }
    }
    float A1 = 0.f, h = 0.f, A2 = 0.f, s = 0.f;
    if (tid < 64) {
        A1 = expf(-expf(nu_log[tid]));
        h = carr[bc * 64 + tid];
        if (MODE != 2) A2 = expf(-expf(nu_nx[tid]));
    }
    __syncthreads();
    if (MODE == 2) {
        if (tid < 64) {
            float a = 0.f;
#pragma unroll
            for (int j = 0; j < 64; j++) a = fmaf(wtW[tid * 64 + j], W2s[j], a);
            WLO[tid] = a;
        }
        if (tid == 0) {
            float a = 0.f;
#pragma unroll
            for (int j = 0; j < 64; j++) a = fmaf(W2s[j], BLs[j], a);
            AUX[0] = a;
        }
    }

    for (int tl = 0; tl < NTIL; tl++) {
        __syncthreads();
        const size_t toff = ((size_t)bc * NTIL + tl) * (64 * TILE);
        const long tokb = tokbase + (long)tl * TILE;

        // load Bu tile -> BUF (swizzled)
#pragma unroll
        for (int it = 0; it < 16; it++) {
            int idx = it * 512 + tid * 4;
            int row = idx >> 7, lq = (idx >> 2) & 31;
            *(float4*)(BUF + row * PB + 4 * (lq ^ ((row >> 2) & 7))) =
                *(const float4*)(bu + toff + idx);
        }
        if (MODE == 0) XS[tid] = xin[tokb + tid];
        __syncthreads();

        // sequential scan: BUF <- hprev (in logical token order)
        if (tid < 64) {
            float* r = BUF + tid * PB;
            const int m = (tid >> 2) & 7;
#pragma unroll 8
            for (int q = 0; q < 32; q++) {
                float4* p = (float4*)(r + 4 * (q ^ m));
                float4 v = *p; float4 o;
                o.x = h; h = fmaf(A1, h, v.x);
                o.y = h; h = fmaf(A1, h, v.y);
                o.z = h; h = fmaf(A1, h, v.z);
                o.w = h; h = fmaf(A1, h, v.w);
                *p = o;
            }
        }
        __syncthreads();

        // GEMM1: y = hprev @ Cm^T ; z = tanh~(y + Dv*u)
        ull acc[4][8];
#pragma unroll
        for (int q = 0; q < 8; q++)
#pragma unroll
            for (int ii = 0; ii < 4; ii++) acc[ii][q] = 0ull;
        gemm8x8(BUF, wtC, g_t, g_n, acc);
#pragma unroll
        for (int q = 0; q < 8; q++) {
            const int jq = (q < 4) ? 4 * g_n + q : 28 + 4 * g_n + q;
            ull dvp = dup2(DVs[jq]);
            ull up[4];
            ldu<MODE>(up, uin, toff, jq, i0, XS, W2s[jq]);
#pragma unroll
            for (int ii = 0; ii < 4; ii++) {
                ull y = acc[ii][q];
                fma2(y, dvp, up[ii]);
                float2 f = unp(y);
                f.x = f.x * rsqrtf(fmaf(f.x, f.x, 1.0f));
                f.y = f.y * rsqrtf(fmaf(f.y, f.y, 1.0f));
                acc[ii][q] = pk(f.x, f.y);
            }
        }
        __syncthreads();
        stile(BUF, g_t, g_n, acc);   // BUF <- z
        __syncthreads();

        if (MODE == 2) {
            // out[t] = WLO.z + Wout.bl + Wout.u
            const int tq = tid >> 2, te = tid & 3;
            float rs = AUX[0];
            const float* up = uin + toff + tid;
#pragma unroll 8
            for (int k = 0; k < 64; k++) {
                float zv = BUF[k * PB + 4 * (tq ^ ((k >> 2) & 7)) + te];
                rs = fmaf(WLO[k], zv, rs);
                rs = fmaf(W2s[k], up[k * TILE], rs);
            }
            uout[tokb + tid] = rs;
            continue;
        }

        // GEMM2: o = z @ Wl^T + bl + u
        ull o2[4][8];
#pragma unroll
        for (int q = 0; q < 8; q++)
#pragma unroll
            for (int ii = 0; ii < 4; ii++) o2[ii][q] = 0ull;
        gemm8x8(BUF, wtW, g_t, g_n, o2);
#pragma unroll
        for (int q = 0; q < 8; q++) {
            const int jq = (q < 4) ? 4 * g_n + q : 28 + 4 * g_n + q;
            ull blp = dup2(BLs[jq]);
            ull up[4];
            ldu<MODE>(up, uin, toff, jq, i0, XS, W2s[jq]);
#pragma unroll
            for (int ii = 0; ii < 4; ii++)
                o2[ii][q] = add2(o2[ii][q], add2(up[ii], blp));
        }
        __syncthreads();
        stile(BUF, g_t, g_n, o2);    // BUF <- u_next
        __syncthreads();

        // stream u_next to gmem (coalesced) + GEMM3: Bu_next = u_next @ (g*Bm)^T
#pragma unroll
        for (int it = 0; it < 16; it++) {
            int idx = it * 512 + tid * 4;
            int row = idx >> 7, lq = (idx >> 2) & 31;
            *(float4*)(uout + toff + idx) =
                *(const float4*)(BUF + row * PB + 4 * (lq ^ ((row >> 2) & 7)));
        }
        ull b3[4][8];
#pragma unroll
        for (int q = 0; q < 8; q++)
#pragma unroll
            for (int ii = 0; ii < 4; ii++) b3[ii][q] = 0ull;
        gemm8x8(BUF, wtB, g_t, g_n, b3);
        __syncthreads();
        stile(BUF, g_t, g_n, b3);    // BUF <- Bu_next
        __syncthreads();

        // store Bu_next + running end-state scan for next layer
#pragma unroll
        for (int it = 0; it < 16; it++) {
            int idx = it * 512 + tid * 4;
            int row = idx >> 7, lq = (idx >> 2) & 31;
            *(float4*)(bu + toff + idx) =
                *(const float4*)(BUF + row * PB + 4 * (lq ^ ((row >> 2) & 7)));
        }
        if (tid < 64) {
            const float* r = BUF + tid * PB;
            const int m = (tid >> 2) & 7;
#pragma unroll 8
            for (int q = 0; q < 32; q++) {
                float4 v = *(const float4*)(r + 4 * (q ^ m));
                s = fmaf(A2, s, v.x); s = fmaf(A2, s, v.y);
                s = fmaf(A2, s, v.z); s = fmaf(A2, s, v.w);
            }
        }
    }
    if (MODE != 2 && tid < 64) ends[bc * 64 + tid] = s;
}

// ---------------------------------------------------------------------------
extern "C" void kernel_launch(void* const* d_in, const int* in_sizes, int n_in,
                              void* d_out, int out_size) {
    (void)in_sizes; (void)n_in; (void)out_size;
    const float* x   = (const float*)d_in[0];
    const float* Win = (const float*)d_in[1];
    const float* nu  = (const float*)d_in[2];
    const float* ga  = (const float*)d_in[3];
    const float* Bm  = (const float*)d_in[4];
    const float* Cm  = (const float*)d_in[5];
    const float* Dv  = (const float*)d_in[6];
    const float* Wl  = (const float*)d_in[7];
    const float* bl  = (const float*)d_in[8];
    const float* Wo  = (const float*)d_in[9];
    float* out = (float*)d_out;

    float *u, *bu, *ends, *carr;
    cudaGetSymbolAddress((void**)&u, g_u);
    cudaGetSymbolAddress((void**)&bu, g_bu);
    cudaGetSymbolAddress((void**)&ends, g_ends);
    cudaGetSymbolAddress((void**)&carr, g_carr);

    static int inited = 0;
    if (!inited) {
        cudaFuncSetAttribute(k_apply<0>, cudaFuncAttributeMaxDynamicSharedMemorySize, SMEMB);
        cudaFuncSetAttribute(k_apply<1>, cudaFuncAttributeMaxDynamicSharedMemorySize, SMEMB);
        cudaFuncSetAttribute(k_apply<2>, cudaFuncAttributeMaxDynamicSharedMemorySize, SMEMB);
        inited = 1;
    }

    const dim3 grid(B_ * CHUNKS), blk(128);
    const int HH = 64 * 64;

    k_init<<<grid, blk>>>(x, bu, ends, Bm, nu, ga, Win);

    k_combine<<<B_, 64>>>(ends, carr, nu);
    k_apply<0><<<grid, blk, SMEMB>>>(x, u, u, bu, carr, ends,
                                     Cm, Wl, Dv, bl, nu, Win, Wo,
                                     Bm + HH, ga + 64, nu + 64);
    k_combine<<<B_, 64>>>(ends, carr, nu + 64);
    k_apply<1><<<grid, blk, SMEMB>>>(x, u, u, bu, carr, ends,
                                     Cm + HH, Wl + HH, Dv + 64, bl + 64,
                                     nu + 64, Win, Wo,
                                     Bm + 2 * HH, ga + 128, nu + 128);
    k_combine<<<B_, 64>>>(ends, carr, nu + 128);
    k_apply<1><<<grid, blk, SMEMB>>>(x, u, u, bu, carr, ends,
                                     Cm + 2 * HH, Wl + 2 * HH, Dv + 128, bl + 128,
                                     nu + 128, Win, Wo,
                                     Bm + 3 * HH, ga + 192, nu + 192);
    k_combine<<<B_, 64>>>(ends, carr, nu + 192);
    k_apply<2><<<grid, blk, SMEMB>>>(x, u, out, bu, carr, ends,
                                     Cm + 3 * HH, Wl + 3 * HH, Dv + 192, bl + 192,
                                     nu + 192, Win, Wo,
                                     Bm, ga, nu);
}

// round 5
// speedup vs baseline: 3.6149x; 1.0350x over previous
#include <cuda_runtime.h>

#define B_     16
#define T_     65536
#define CHUNKS 128
#define L_     512
#define TILE   128
#define NTIL   4
#define PB     132
typedef unsigned long long ull;

__device__ float g_u [(size_t)B_ * T_ * 64];
__device__ float g_bu[(size_t)B_ * T_ * 64];
__device__ float g_ends[B_ * CHUNKS * 64];
__device__ float g_carr[B_ * CHUNKS * 64];
__device__ float g_cX[64];     // layer-0: gam0 * (Bm0 @ Win)
__device__ float g_wlo[64];    // last layer: Wout @ Wl3  (over j)
__device__ float g_aux[1];     // Wout . bl3

__device__ __forceinline__ void fma2(ull& d, ull a, ull b) {
    asm("fma.rn.f32x2 %0, %1, %2, %0;" : "+l"(d) : "l"(a), "l"(b));
}
__device__ __forceinline__ ull add2(ull a, ull b) {
    ull d; asm("add.rn.f32x2 %0, %1, %2;" : "=l"(d) : "l"(a), "l"(b)); return d;
}
__device__ __forceinline__ ull mul2(ull a, ull b) {
    ull d; asm("mul.rn.f32x2 %0, %1, %2;" : "=l"(d) : "l"(a), "l"(b)); return d;
}
__device__ __forceinline__ ull dup2(float x) {
    ull r; asm("mov.b64 %0, {%1, %1};" : "=l"(r) : "f"(x)); return r;
}
__device__ __forceinline__ float2 unp(ull p) {
    float2 r; asm("mov.b64 {%0, %1}, %2;" : "=f"(r.x), "=f"(r.y) : "l"(p)); return r;
}
__device__ __forceinline__ ull pk(float a, float b) {
    ull r; asm("mov.b64 %0, {%1, %2};" : "=l"(r) : "f"(a), "f"(b)); return r;
}

// 8tok x 8n register-tile GEMM over 64 k. BUF: [k][128 tok] rows pitch PB,
// quad q swizzled as q ^ ((k>>2)&7). wt: [k][n] pitch 64.
__device__ __forceinline__ void gemm8x8(const float* __restrict__ BUF,
                                        const float* __restrict__ wt,
                                        int g_t, int g_n, ull acc[4][8]) {
#pragma unroll 4
    for (int k = 0; k < 64; k++) {
        const int m = (k >> 2) & 7;
        const float* r = BUF + k * PB;
        ulonglong2 a0 = *(const ulonglong2*)(r + 4 * ((2 * g_t) ^ m));
        ulonglong2 a1 = *(const ulonglong2*)(r + 4 * ((2 * g_t + 1) ^ m));
        float4 b0 = *(const float4*)(wt + k * 64 + 4 * g_n);
        float4 b1 = *(const float4*)(wt + k * 64 + 32 + 4 * g_n);
        ull ap[4] = {a0.x, a0.y, a1.x, a1.y};
        ull bb[8] = {dup2(b0.x), dup2(b0.y), dup2(b0.z), dup2(b0.w),
                     dup2(b1.x), dup2(b1.y), dup2(b1.z), dup2(b1.w)};
#pragma unroll
        for (int q = 0; q < 8; q++)
#pragma unroll
            for (int ii = 0; ii < 4; ii++) fma2(acc[ii][q], ap[ii], bb[q]);
    }
}

__device__ __forceinline__ void stile(float* __restrict__ BUF, int g_t, int g_n,
                                      const ull acc[4][8]) {
#pragma unroll
    for (int q = 0; q < 8; q++) {
        const int jq = (q < 4) ? 4 * g_n + q : 28 + 4 * g_n + q;
        const int mj = (jq >> 2) & 7;
        ulonglong2 v0; v0.x = acc[0][q]; v0.y = acc[1][q];
        ulonglong2 v1; v1.x = acc[2][q]; v1.y = acc[3][q];
        *(ulonglong2*)(BUF + jq * PB + 4 * ((2 * g_t) ^ mj)) = v0;
        *(ulonglong2*)(BUF + jq * PB + 4 * ((2 * g_t + 1) ^ mj)) = v1;
    }
}

template <int MODE>
__device__ __forceinline__ void ldu(ull up[4], const float* __restrict__ uin,
                                    size_t toff, int jq, int i0,
                                    const float* __restrict__ XS, float w) {
    if (MODE == 0) {
        ull wp = dup2(w);
        up[0] = mul2(wp, *(const ull*)(XS + i0));
        up[1] = mul2(wp, *(const ull*)(XS + i0 + 2));
        up[2] = mul2(wp, *(const ull*)(XS + i0 + 4));
        up[3] = mul2(wp, *(const ull*)(XS + i0 + 6));
    } else {
        const float* p = uin + toff + (size_t)jq * TILE + i0;
        ulonglong2 a = *(const ulonglong2*)p;
        ulonglong2 b = *(const ulonglong2*)(p + 4);
        up[0] = a.x; up[1] = a.y; up[2] = b.x; up[3] = b.y;
    }
}

// ---------------------------------------------------------------------------
// k_prep: one block; computes cX (layer-0 Bu coefficient), WLO, Wout.bl3.
// ---------------------------------------------------------------------------
__global__ void __launch_bounds__(64)
k_prep(const float* __restrict__ Bm0, const float* __restrict__ ga0,
       const float* __restrict__ Win, const float* __restrict__ Wl3,
       const float* __restrict__ bl3, const float* __restrict__ Wout) {
    const int n = threadIdx.x;
    float a = 0.f;
#pragma unroll
    for (int k = 0; k < 64; k++) a = fmaf(Bm0[n * 64 + k], Win[k], a);
    g_cX[n] = expf(ga0[n]) * a;
    float w = 0.f;
#pragma unroll
    for (int j = 0; j < 64; j++) w = fmaf(Wout[j], Wl3[j * 64 + n], w);
    g_wlo[n] = w;
    if (n == 0) {
        float s = 0.f;
#pragma unroll
        for (int j = 0; j < 64; j++) s = fmaf(Wout[j], bl3[j], s);
        g_aux[0] = s;
    }
}

// ---------------------------------------------------------------------------
// k_init: layer-0 chunk end states only (Bu0 is rank-1; never materialized).
// ---------------------------------------------------------------------------
__global__ void __launch_bounds__(128)
k_init(const float* __restrict__ x, float* __restrict__ ends,
       const float* __restrict__ nu_log) {
    __shared__ float xs[TILE];
    const int tid = threadIdx.x;
    const int bc = blockIdx.x;
    const long tokbase = (long)(bc / CHUNKS) * T_ + (long)(bc % CHUNKS) * L_;

    float A = 0.f, s = 0.f;
    if (tid < 64) A = expf(-expf(nu_log[tid]));
    for (int tl = 0; tl < NTIL; tl++) {
        __syncthreads();
        xs[tid] = x[tokbase + tl * TILE + tid];
        __syncthreads();
        if (tid < 64) {
#pragma unroll 8
            for (int t = 0; t < TILE; t++) s = fmaf(A, s, xs[t]);
        }
    }
    if (tid < 64) ends[bc * 64 + tid] = g_cX[tid] * s;
}

__global__ void k_combine(const float* __restrict__ ends,
                          float* __restrict__ carries,
                          const float* __restrict__ nu_log) {
    const int b = blockIdx.x, n = threadIdx.x;
    const float AL = expf(-expf(nu_log[n]) * (float)L_);
    float carry = 0.f;
#pragma unroll 8
    for (int c = 0; c < CHUNKS; c++) {
        carries[(b * CHUNKS + c) * 64 + n] = carry;
        carry = fmaf(AL, carry, ends[(b * CHUNKS + c) * 64 + n]);
    }
}

// ---------------------------------------------------------------------------
// Fused per-layer kernel. MODE 0: first layer (u = Win*x, Bu synthesized from
// x). MODE 1: middle. MODE 2: last (fold Wout analytically).
// REV: walk chunks in reverse for L2 reuse against the producer kernel.
// ---------------------------------------------------------------------------
#define SMEMB 85008

template <int MODE, int REV>
__global__ void __launch_bounds__(128, 2)
k_apply(const float* __restrict__ xin, const float* __restrict__ uin,
        float* __restrict__ uout, float* __restrict__ bu,
        const float* __restrict__ carr, float* __restrict__ ends,
        const float* __restrict__ Cm, const float* __restrict__ Wl,
        const float* __restrict__ Dv, const float* __restrict__ bl,
        const float* __restrict__ nu_log, const float* __restrict__ Win,
        const float* __restrict__ Wout, const float* __restrict__ Bm_nx,
        const float* __restrict__ ga_nx, const float* __restrict__ nu_nx) {
    extern __shared__ __align__(16) float sm[];
    float* wtC = sm;            // [k][n] 4096
    float* wtW = sm + 4096;
    float* wtB = sm + 8192;
    float* BUF = sm + 12288;    // 64 * PB
    float* XS  = sm + 20736;    // 128
    float* DVs = sm + 20864;
    float* BLs = DVs + 64;
    float* W2s = BLs + 64;
    float* WLO = W2s + 64;
    float* GMs = WLO + 64;
    float* AUX = GMs + 64;      // 4
    float* CXs = AUX + 4;       // 64

    const int tid = threadIdx.x;
    const int g_t = tid >> 3, g_n = tid & 7;
    const int i0 = g_t * 8;
    const int bc = REV ? (int)(gridDim.x - 1 - blockIdx.x) : (int)blockIdx.x;
    const long tokbase = (long)(bc / CHUNKS) * T_ + (long)(bc % CHUNKS) * L_;

    if (tid < 64) {
        DVs[tid] = Dv[tid];
        BLs[tid] = bl[tid];
        W2s[tid] = (MODE == 0) ? Win[tid] : ((MODE == 2) ? Wout[tid] : 0.f);
        GMs[tid] = (MODE != 2) ? expf(ga_nx[tid]) : 0.f;
        if (MODE == 0) CXs[tid] = g_cX[tid];
        if (MODE == 2) WLO[tid] = g_wlo[tid];
        if (MODE == 2 && tid == 0) AUX[0] = g_aux[0];
    }
    __syncthreads();
    {
        const int r = tid & 63;
        const float* src = (tid < 64) ? Cm : Wl;
        float* dst = (tid < 64) ? wtC : wtW;
#pragma unroll 4
        for (int kq = 0; kq < 16; kq++) {
            float4 w = *(const float4*)(src + r * 64 + kq * 4);
            dst[(kq * 4 + 0) * 64 + r] = w.x;
            dst[(kq * 4 + 1) * 64 + r] = w.y;
            dst[(kq * 4 + 2) * 64 + r] = w.z;
            dst[(kq * 4 + 3) * 64 + r] = w.w;
        }
        if (MODE != 2 && tid < 64) {
            const float g = GMs[r];
#pragma unroll 4
            for (int kq = 0; kq < 16; kq++) {
                float4 w = *(const float4*)(Bm_nx + r * 64 + kq * 4);
                wtB[(kq * 4 + 0) * 64 + r] = g * w.x;
                wtB[(kq * 4 + 1) * 64 + r] = g * w.y;
                wtB[(kq * 4 + 2) * 64 + r] = g * w.z;
                wtB[(kq * 4 + 3) * 64 + r] = g * w.w;
            }
        }
    }
    float A1 = 0.f, h = 0.f, A2 = 0.f, s = 0.f;
    if (tid < 64) {
        A1 = expf(-expf(nu_log[tid]));
        h = carr[bc * 64 + tid];
        if (MODE != 2) A2 = expf(-expf(nu_nx[tid]));
    }
    __syncthreads();

    for (int tl = 0; tl < NTIL; tl++) {
        __syncthreads();
        const size_t toff = ((size_t)bc * NTIL + tl) * (64 * TILE);
        const long tokb = tokbase + (long)tl * TILE;

        if (MODE == 0) {
            // synthesize Bu0 tile from x (rank-1), no gmem bu traffic
            XS[tid] = xin[tokb + tid];
            __syncthreads();
#pragma unroll
            for (int it = 0; it < 16; it++) {
                int idx = it * 512 + tid * 4;
                int row = idx >> 7, col = idx & 127;
                float c = CXs[row];
                float4 v = make_float4(c * XS[col], c * XS[col + 1],
                                       c * XS[col + 2], c * XS[col + 3]);
                *(float4*)(BUF + row * PB +
                           4 * ((col >> 2) ^ ((row >> 2) & 7))) = v;
            }
        } else {
#pragma unroll
            for (int it = 0; it < 16; it++) {
                int idx = it * 512 + tid * 4;
                int row = idx >> 7, lq = (idx >> 2) & 31;
                *(float4*)(BUF + row * PB + 4 * (lq ^ ((row >> 2) & 7))) =
                    *(const float4*)(bu + toff + idx);
            }
        }
        __syncthreads();

        // sequential scan: BUF <- hprev
        if (tid < 64) {
            float* r = BUF + tid * PB;
            const int m = (tid >> 2) & 7;
#pragma unroll 8
            for (int q = 0; q < 32; q++) {
                float4* p = (float4*)(r + 4 * (q ^ m));
                float4 v = *p; float4 o;
                o.x = h; h = fmaf(A1, h, v.x);
                o.y = h; h = fmaf(A1, h, v.y);
                o.z = h; h = fmaf(A1, h, v.z);
                o.w = h; h = fmaf(A1, h, v.w);
                *p = o;
            }
        }
        __syncthreads();

        // GEMM1: y = hprev @ Cm^T ; z = tanh~(y + Dv*u)
        ull acc[4][8];
#pragma unroll
        for (int q = 0; q < 8; q++)
#pragma unroll
            for (int ii = 0; ii < 4; ii++) acc[ii][q] = 0ull;
        gemm8x8(BUF, wtC, g_t, g_n, acc);
#pragma unroll
        for (int q = 0; q < 8; q++) {
            const int jq = (q < 4) ? 4 * g_n + q : 28 + 4 * g_n + q;
            ull dvp = dup2(DVs[jq]);
            ull up[4];
            ldu<MODE>(up, uin, toff, jq, i0, XS, W2s[jq]);
#pragma unroll
            for (int ii = 0; ii < 4; ii++) {
                ull y = acc[ii][q];
                fma2(y, dvp, up[ii]);
                float2 f = unp(y);
                f.x = f.x * rsqrtf(fmaf(f.x, f.x, 1.0f));
                f.y = f.y * rsqrtf(fmaf(f.y, f.y, 1.0f));
                acc[ii][q] = pk(f.x, f.y);
            }
        }
        __syncthreads();
        stile(BUF, g_t, g_n, acc);   // BUF <- z
        __syncthreads();

        if (MODE == 2) {
            const int tq = tid >> 2, te = tid & 3;
            float rs = AUX[0];
            const float* up = uin + toff + tid;
#pragma unroll 8
            for (int k = 0; k < 64; k++) {
                float zv = BUF[k * PB + 4 * (tq ^ ((k >> 2) & 7)) + te];
                rs = fmaf(WLO[k], zv, rs);
                rs = fmaf(W2s[k], up[k * TILE], rs);
            }
            uout[tokb + tid] = rs;
            continue;
        }

        // GEMM2: o = z @ Wl^T + bl + u
        ull o2[4][8];
#pragma unroll
        for (int q = 0; q < 8; q++)
#pragma unroll
            for (int ii = 0; ii < 4; ii++) o2[ii][q] = 0ull;
        gemm8x8(BUF, wtW, g_t, g_n, o2);
#pragma unroll
        for (int q = 0; q < 8; q++) {
            const int jq = (q < 4) ? 4 * g_n + q : 28 + 4 * g_n + q;
            ull blp = dup2(BLs[jq]);
            ull up[4];
            ldu<MODE>(up, uin, toff, jq, i0, XS, W2s[jq]);
#pragma unroll
            for (int ii = 0; ii < 4; ii++)
                o2[ii][q] = add2(o2[ii][q], add2(up[ii], blp));
        }
        __syncthreads();
        stile(BUF, g_t, g_n, o2);    // BUF <- u_next
        __syncthreads();

        // stream u_next out + GEMM3: Bu_next = u_next @ (g*Bm)^T
#pragma unroll
        for (int it = 0; it < 16; it++) {
            int idx = it * 512 + tid * 4;
            int row = idx >> 7, lq = (idx >> 2) & 31;
            *(float4*)(uout + toff + idx) =
                *(const float4*)(BUF + row * PB + 4 * (lq ^ ((row >> 2) & 7)));
        }
        ull b3[4][8];
#pragma unroll
        for (int q = 0; q < 8; q++)
#pragma unroll
            for (int ii = 0; ii < 4; ii++) b3[ii][q] = 0ull;
        gemm8x8(BUF, wtB, g_t, g_n, b3);
        __syncthreads();
        stile(BUF, g_t, g_n, b3);    // BUF <- Bu_next
        __syncthreads();

#pragma unroll
        for (int it = 0; it < 16; it++) {
            int idx = it * 512 + tid * 4;
            int row = idx >> 7, lq = (idx >> 2) & 31;
            *(float4*)(bu + toff + idx) =
                *(const float4*)(BUF + row * PB + 4 * (lq ^ ((row >> 2) & 7)));
        }
        if (tid < 64) {
            const float* r = BUF + tid * PB;
            const int m = (tid >> 2) & 7;
#pragma unroll 8
            for (int q = 0; q < 32; q++) {
                float4 v = *(const float4*)(r + 4 * (q ^ m));
                s = fmaf(A2, s, v.x); s = fmaf(A2, s, v.y);
                s = fmaf(A2, s, v.z); s = fmaf(A2, s, v.w);
            }
        }
    }
    if (MODE != 2 && tid < 64) ends[bc * 64 + tid] = s;
}

// ---------------------------------------------------------------------------
extern "C" void kernel_launch(void* const* d_in, const int* in_sizes, int n_in,
                              void* d_out, int out_size) {
    (void)in_sizes; (void)n_in; (void)out_size;
    const float* x   = (const float*)d_in[0];
    const float* Win = (const float*)d_in[1];
    const float* nu  = (const float*)d_in[2];
    const float* ga  = (const float*)d_in[3];
    const float* Bm  = (const float*)d_in[4];
    const float* Cm  = (const float*)d_in[5];
    const float* Dv  = (const float*)d_in[6];
    const float* Wl  = (const float*)d_in[7];
    const float* bl  = (const float*)d_in[8];
    const float* Wo  = (const float*)d_in[9];
    float* out = (float*)d_out;

    float *u, *bu, *ends, *carr;
    cudaGetSymbolAddress((void**)&u, g_u);
    cudaGetSymbolAddress((void**)&bu, g_bu);
    cudaGetSymbolAddress((void**)&ends, g_ends);
    cudaGetSymbolAddress((void**)&carr, g_carr);

    static int inited = 0;
    if (!inited) {
        cudaFuncSetAttribute(k_apply<0,0>, cudaFuncAttributeMaxDynamicSharedMemorySize, SMEMB);
        cudaFuncSetAttribute(k_apply<1,1>, cudaFuncAttributeMaxDynamicSharedMemorySize, SMEMB);
        cudaFuncSetAttribute(k_apply<1,0>, cudaFuncAttributeMaxDynamicSharedMemorySize, SMEMB);
        cudaFuncSetAttribute(k_apply<2,1>, cudaFuncAttributeMaxDynamicSharedMemorySize, SMEMB);
        inited = 1;
    }

    const dim3 grid(B_ * CHUNKS), blk(128);
    const int HH = 64 * 64;

    k_prep<<<1, 64>>>(Bm, ga, Win, Wl + 3 * HH, bl + 192, Wo);
    k_init<<<grid, blk>>>(x, ends, nu);
    k_combine<<<B_, 64>>>(ends, carr, nu);
    k_apply<0,0><<<grid, blk, SMEMB>>>(x, u, u, bu, carr, ends,
                                       Cm, Wl, Dv, bl, nu, Win, Wo,
                                       Bm + HH, ga + 64, nu + 64);
    k_combine<<<B_, 64>>>(ends, carr, nu + 64);
    k_apply<1,1><<<grid, blk, SMEMB>>>(x, u, u, bu, carr, ends,
                                       Cm + HH, Wl + HH, Dv + 64, bl + 64,
                                       nu + 64, Win, Wo,
                                       Bm + 2 * HH, ga + 128, nu + 128);
    k_combine<<<B_, 64>>>(ends, carr, nu + 128);
    k_apply<1,0><<<grid, blk, SMEMB>>>(x, u, u, bu, carr, ends,
                                       Cm + 2 * HH, Wl + 2 * HH, Dv + 128, bl + 128,
                                       nu + 128, Win, Wo,
                                       Bm + 3 * HH, ga + 192, nu + 192);
    k_combine<<<B_, 64>>>(ends, carr, nu + 192);
    k_apply<2,1><<<grid, blk, SMEMB>>>(x, u, out, bu, carr, ends,
                                       Cm + 3 * HH, Wl + 3 * HH, Dv + 192, bl + 192,
                                       nu + 192, Win, Wo,
                                       Bm, ga, nu);
}